// round 1
// baseline (speedup 1.0000x reference)
#include <cuda_runtime.h>
#include <cstdint>

#define Bb    8
#define C_INN 12
#define CQ    36
#define NN    4096
#define SCALE 0.28867513459481287f   /* 1/sqrt(12) */

typedef unsigned long long u64;

/* ---------------- scratch (device globals; no allocation allowed) -------- */
__device__ float g_q [Bb*CQ*NN];
__device__ float g_k [Bb*CQ*NN];
__device__ float g_v [Bb*CQ*NN];
__device__ float g_vp[Bb*CQ*NN];   /* v / D[n] */
__device__ float g_M [Bb*NN];      /* row max of scaled scores */

/* ---------------- packed f32x2 helpers (FFMA2 path, sm_103a) ------------- */
__device__ __forceinline__ u64 pk(float lo, float hi){
    u64 r;
    asm("mov.b64 %0, {%1,%2};" : "=l"(r)
        : "r"(__float_as_uint(lo)), "r"(__float_as_uint(hi)));
    return r;
}
__device__ __forceinline__ void upk(u64 v, float& lo, float& hi){
    unsigned a, b;
    asm("mov.b64 {%0,%1}, %2;" : "=r"(a), "=r"(b) : "l"(v));
    lo = __uint_as_float(a); hi = __uint_as_float(b);
}
__device__ __forceinline__ void fma2(u64& d, u64 a, u64 b){
    asm("fma.rn.f32x2 %0, %1, %2, %3;" : "=l"(d) : "l"(a), "l"(b), "l"(d));
}

/* ================= Kernel A: fused QKV projection ======================== */
__global__ __launch_bounds__(128)
void qkv_kernel(const float* __restrict__ x,
                const float* __restrict__ wq, const float* __restrict__ bq,
                const float* __restrict__ wk, const float* __restrict__ bk,
                const float* __restrict__ wv, const float* __restrict__ bv)
{
    __shared__ float wq_s[CQ*C_INN], wk_s[CQ*C_INN], wv_s[CQ*C_INN];
    __shared__ float bq_s[CQ], bk_s[CQ], bv_s[CQ];
    const int t = threadIdx.x;
    for (int i = t; i < CQ*C_INN; i += 128){ wq_s[i]=wq[i]; wk_s[i]=wk[i]; wv_s[i]=wv[i]; }
    if (t < CQ){ bq_s[t]=bq[t]; bk_s[t]=bk[t]; bv_s[t]=bv[t]; }
    __syncthreads();

    const int b = blockIdx.y;
    const int n = blockIdx.x*128 + t;

    float xv[C_INN];
    #pragma unroll
    for (int c = 0; c < C_INN; ++c) xv[c] = x[(b*C_INN + c)*NN + n];

    #pragma unroll 4
    for (int o = 0; o < CQ; ++o){
        float q = bq_s[o], k = bk_s[o], v = bv_s[o];
        #pragma unroll
        for (int c = 0; c < C_INN; ++c){
            const float xc = xv[c];
            q += wq_s[o*C_INN+c]*xc;
            k += wk_s[o*C_INN+c]*xc;
            v += wv_s[o*C_INN+c]*xc;
        }
        const int idx = (b*CQ + o)*NN + n;
        g_q[idx] = q*SCALE;   /* fold score scale into q */
        g_k[idx] = k;
        g_v[idx] = v;
    }
}

/* ====== Kernel B: row stats (M[n], D[n]) over all m; writes vp = v/D ===== */
__global__ __launch_bounds__(256)
void stats_kernel()
{
    __shared__ float k_s[CQ*128];
    __shared__ float q_s[CQ*128];
    __shared__ float invd_s[128];

    const int t  = threadIdx.x;
    const int b  = blockIdx.y;
    const int n0 = blockIdx.x*128;

    for (int i = t; i < CQ*128; i += 256){
        const int c = i >> 7, j = i & 127;
        k_s[i] = g_k[(b*CQ + c)*NN + n0 + j];
    }

    const int ty = t >> 4, tx = t & 15;
    const int ro = ty*8,  co = tx*8;

    float rm[8], rs[8];
    #pragma unroll
    for (int i = 0; i < 8; ++i){ rm[i] = -1e30f; rs[i] = 0.f; }

    for (int mc = 0; mc < NN/128; ++mc){
        __syncthreads();
        for (int i = t; i < CQ*128; i += 256){
            const int c = i >> 7, j = i & 127;
            q_s[i] = g_q[(b*CQ + c)*NN + mc*128 + j];
        }
        __syncthreads();

        u64 acc[8][4];
        #pragma unroll
        for (int i = 0; i < 8; ++i)
            #pragma unroll
            for (int j = 0; j < 4; ++j) acc[i][j] = 0ull;

        #pragma unroll 4
        for (int c = 0; c < CQ; ++c){
            const float4 a0 = *(const float4*)(k_s + c*128 + ro);
            const float4 a1 = *(const float4*)(k_s + c*128 + ro + 4);
            const ulonglong2 b01 = *(const ulonglong2*)(q_s + c*128 + co);
            const ulonglong2 b23 = *(const ulonglong2*)(q_s + c*128 + co + 4);
            const float av[8] = {a0.x,a0.y,a0.z,a0.w,a1.x,a1.y,a1.z,a1.w};
            #pragma unroll
            for (int i = 0; i < 8; ++i){
                const u64 ad = pk(av[i], av[i]);
                fma2(acc[i][0], ad, b01.x);
                fma2(acc[i][1], ad, b01.y);
                fma2(acc[i][2], ad, b23.x);
                fma2(acc[i][3], ad, b23.y);
            }
        }

        /* online softmax update for this thread's 8 rows */
        #pragma unroll
        for (int i = 0; i < 8; ++i){
            float s[8];
            upk(acc[i][0], s[0], s[1]);
            upk(acc[i][1], s[2], s[3]);
            upk(acc[i][2], s[4], s[5]);
            upk(acc[i][3], s[6], s[7]);
            const float m8 = fmaxf(fmaxf(fmaxf(s[0],s[1]), fmaxf(s[2],s[3])),
                                   fmaxf(fmaxf(s[4],s[5]), fmaxf(s[6],s[7])));
            const float mn = fmaxf(rm[i], m8);
            float sum = 0.f;
            #pragma unroll
            for (int j = 0; j < 8; ++j) sum += __expf(s[j] - mn);
            rs[i] = rs[i]*__expf(rm[i] - mn) + sum;
            rm[i] = mn;
        }
    }

    /* reduce the 16 column-group partials per row (reuse q_s) */
    __syncthreads();
    float* rmax_s = q_s;
    float* rsum_s = q_s + 2048;
    #pragma unroll
    for (int i = 0; i < 8; ++i){
        rmax_s[tx*128 + ro + i] = rm[i];
        rsum_s[tx*128 + ro + i] = rs[i];
    }
    __syncthreads();
    if (t < 128){
        float M = -1e30f;
        #pragma unroll
        for (int j = 0; j < 16; ++j) M = fmaxf(M, rmax_s[j*128 + t]);
        float D = 0.f;
        #pragma unroll
        for (int j = 0; j < 16; ++j) D += rsum_s[j*128 + t]*__expf(rmax_s[j*128 + t] - M);
        g_M[b*NN + n0 + t] = M;
        invd_s[t] = 1.f / D;
    }
    __syncthreads();
    for (int i = t; i < CQ*128; i += 256){
        const int c = i >> 7, j = i & 127;
        const int idx = (b*CQ + c)*NN + n0 + j;
        g_vp[idx] = g_v[idx]*invd_s[j];
    }
}

/* ====== Kernel C: recompute scores, weight V, apply output projection ==== */
__global__ __launch_bounds__(512)
void attn_out_kernel(const float* __restrict__ wo, const float* __restrict__ bo,
                     float* __restrict__ out)
{
    extern __shared__ float smc[];
    float* q_s  = smc;            /* 4608 : q tile for this block's m columns */
    float* k_s  = q_s  + 4608;    /* 4608 : k chunk (n)                      */
    float* vp_s = k_s  + 4608;    /* 4608 : v/D chunk (n)                    */
    float* M_s  = vp_s + 4608;    /* 128                                     */
    float* wo_s = M_s  + 128;     /* 432                                     */
    float* bo_s = wo_s + 432;     /* 16                                      */
    float* pT   = bo_s + 16;      /* 128*132 : P transposed [m][n], padded   */

    const int t  = threadIdx.x;
    const int b  = blockIdx.y;
    const int m0 = blockIdx.x*128;

    for (int i = t; i < CQ*128; i += 512){
        const int c = i >> 7, j = i & 127;
        q_s[i] = g_q[(b*CQ + c)*NN + m0 + j];
    }
    for (int i = t; i < 432; i += 512) wo_s[i] = wo[i];
    if (t < 12) bo_s[t] = bo[t];

    /* phase-1 mapping: 16(ty over n) x 32(tx over m), 8n x 4m micro-tile */
    const int ty = t >> 5, tx = t & 31;
    const int ro = ty*8,  co = tx*4;
    /* phase-2 mapping: one m column + 9 channels per thread */
    const int m  = t & 127;
    const int cb = (t >> 7)*9;

    u64 acc2[9];
    #pragma unroll
    for (int i = 0; i < 9; ++i) acc2[i] = 0ull;

    for (int nc = 0; nc < NN/128; ++nc){
        __syncthreads();
        for (int i = t; i < CQ*128; i += 512){
            const int c = i >> 7, j = i & 127;
            const int idx = (b*CQ + c)*NN + nc*128 + j;
            k_s[i]  = g_k[idx];
            vp_s[i] = g_vp[idx];
        }
        if (t < 128) M_s[t] = g_M[b*NN + nc*128 + t];
        __syncthreads();

        /* ---- phase 1: s = k.q, p = exp(s - M[n]) -> pT[m][n] ---- */
        {
            u64 sacc[8][2];
            #pragma unroll
            for (int i = 0; i < 8; ++i){ sacc[i][0] = 0ull; sacc[i][1] = 0ull; }
            #pragma unroll 4
            for (int c = 0; c < CQ; ++c){
                const float4 a0 = *(const float4*)(k_s + c*128 + ro);
                const float4 a1 = *(const float4*)(k_s + c*128 + ro + 4);
                const ulonglong2 bb = *(const ulonglong2*)(q_s + c*128 + co);
                const float av[8] = {a0.x,a0.y,a0.z,a0.w,a1.x,a1.y,a1.z,a1.w};
                #pragma unroll
                for (int i = 0; i < 8; ++i){
                    const u64 ad = pk(av[i], av[i]);
                    fma2(sacc[i][0], ad, bb.x);
                    fma2(sacc[i][1], ad, bb.y);
                }
            }
            float p[8][4];
            #pragma unroll
            for (int i = 0; i < 8; ++i){
                float s0,s1,s2,s3;
                upk(sacc[i][0], s0, s1);
                upk(sacc[i][1], s2, s3);
                const float Mn = M_s[ro + i];
                p[i][0] = __expf(s0 - Mn); p[i][1] = __expf(s1 - Mn);
                p[i][2] = __expf(s2 - Mn); p[i][3] = __expf(s3 - Mn);
            }
            #pragma unroll
            for (int j = 0; j < 4; ++j){
                *(float4*)(pT + (co+j)*132 + ro)     = make_float4(p[0][j],p[1][j],p[2][j],p[3][j]);
                *(float4*)(pT + (co+j)*132 + ro + 4) = make_float4(p[4][j],p[5][j],p[6][j],p[7][j]);
            }
        }
        __syncthreads();

        /* ---- phase 2: attn[c,m] += sum_n vp[c,n] * p[n,m] ---- */
        {
            const float* prow = pT + m*132;
            #pragma unroll 2
            for (int n = 0; n < 128; n += 4){
                const ulonglong2 pp = *(const ulonglong2*)(prow + n);
                #pragma unroll
                for (int cc = 0; cc < 9; ++cc){
                    const ulonglong2 vv = *(const ulonglong2*)(vp_s + (cb+cc)*128 + n);
                    fma2(acc2[cc], vv.x, pp.x);
                    fma2(acc2[cc], vv.y, pp.y);
                }
            }
        }
    }

    /* stage attn tile to smem (reuse pT), then output projection */
    __syncthreads();
    float* attn_s = pT;
    #pragma unroll
    for (int cc = 0; cc < 9; ++cc){
        float lo, hi; upk(acc2[cc], lo, hi);
        attn_s[(cb+cc)*132 + m] = lo + hi;
    }
    __syncthreads();
    {
        const int og = t >> 7;       /* 0..3 -> 3 output channels each */
        const int mm = t & 127;
        #pragma unroll
        for (int oo = 0; oo < 3; ++oo){
            const int o = og*3 + oo;
            float acc = bo_s[o];
            #pragma unroll
            for (int c = 0; c < CQ; ++c) acc += wo_s[o*36 + c]*attn_s[c*132 + mm];
            out[(b*C_INN + o)*NN + m0 + mm] = acc;
        }
    }
}

/* ============================== launch =================================== */
extern "C" void kernel_launch(void* const* d_in, const int* in_sizes, int n_in,
                              void* d_out, int out_size)
{
    const float* x  = (const float*)d_in[0];
    const float* wq = (const float*)d_in[1];
    const float* bq = (const float*)d_in[2];
    const float* wk = (const float*)d_in[3];
    const float* bk = (const float*)d_in[4];
    const float* wv = (const float*)d_in[5];
    const float* bv = (const float*)d_in[6];
    const float* wo = (const float*)d_in[7];
    const float* bo = (const float*)d_in[8];
    float* out = (float*)d_out;

    /* 125184 B dynamic smem for kernel C (idempotent host-side attribute) */
    cudaFuncSetAttribute(attn_out_kernel,
                         cudaFuncAttributeMaxDynamicSharedMemorySize, 125184);

    qkv_kernel    <<<dim3(32, 8), 128>>>(x, wq, bq, wk, bk, wv, bv);
    stats_kernel  <<<dim3(32, 8), 256>>>();
    attn_out_kernel<<<dim3(32, 8), 512, 125184>>>(wo, bo, out);
}

// round 3
// speedup vs baseline: 2.5397x; 2.5397x over previous
#include <cuda_runtime.h>
#include <cuda_bf16.h>
#include <cstdint>

#define NN    4096
#define NB    32            /* 4096/128 blocks per batch */
#define PANEL 6144          /* u32 per 128-row fragment panel */
#define SCALE 0.28867513459481287f

typedef unsigned int u32;

/* ------------- global scratch: fragment-order panels --------------------- */
__device__ u32  g_qA[8*NB*PANEL];   /* Q as mma-A fragments (pass2) */
__device__ u32  g_qB[8*NB*PANEL];   /* Q as mma-B fragments (pass1) */
__device__ u32  g_kA[8*NB*PANEL];   /* K as mma-A fragments (pass1) */
__device__ u32  g_kB[8*NB*PANEL];   /* K as mma-B fragments (pass2) */
__device__ u32  g_vB[8*NB*PANEL];   /* v/D as mma-B fragments (pass2 PV) */
__device__ float g_v[8*48*NN];      /* fp32 v, rows 36..47 zero */

/* ------------------------- helpers --------------------------------------- */
__device__ __forceinline__ void mma_bf16(float d[4], const u32 a[4], const u32 b[2]){
    asm("mma.sync.aligned.m16n8k16.row.col.f32.bf16.bf16.f32 "
        "{%0,%1,%2,%3}, {%4,%5,%6,%7}, {%8,%9}, {%0,%1,%2,%3};"
        : "+f"(d[0]), "+f"(d[1]), "+f"(d[2]), "+f"(d[3])
        : "r"(a[0]), "r"(a[1]), "r"(a[2]), "r"(a[3]), "r"(b[0]), "r"(b[1]));
}
__device__ __forceinline__ u32 pk2(float flo, float fhi){  /* {hi:fhi, lo:flo} */
    u32 r; asm("cvt.rn.bf16x2.f32 %0, %1, %2;" : "=r"(r) : "f"(fhi), "f"(flo));
    return r;
}
__device__ __forceinline__ void splitpair(float f0, float f1, u32& hiP, u32& loP){
    __nv_bfloat16 h0 = __float2bfloat16(f0);
    __nv_bfloat16 h1 = __float2bfloat16(f1);
    float r0 = f0 - __bfloat162float(h0);
    float r1 = f1 - __bfloat162float(h1);
    __nv_bfloat16 l0 = __float2bfloat16(r0);
    __nv_bfloat16 l1 = __float2bfloat16(r1);
    hiP = (u32)__bfloat16_as_ushort(h0) | ((u32)__bfloat16_as_ushort(h1) << 16);
    loP = (u32)__bfloat16_as_ushort(l0) | ((u32)__bfloat16_as_ushort(l1) << 16);
}

/* ============ Kernel A: QKV projection + fragment panel writes =========== */
/* A-panel u32 index: ((rt*3+kk)*2+s)*128 + lane*4 + reg
     row r: rt=r>>4, lr=r&15, g=lr&7, half=lr>>3; pair p(0..23): kk=p>>3,
     cp=p&7, tg=cp&3, hi8=cp>>2; reg=(hi8<<1)|half; lane=(g<<2)|tg
   B-panel u32 index: ((ct*3+kk)*2+s)*64 + lane*2 + reg
     col m local lc: ct=lc>>3, g=lc&7; pair p: kk=p>>3, p8=p&7, reg=p8>>2,
     tg=p8&3; lane=(g<<2)|tg                                                 */
__global__ __launch_bounds__(128)
void qkv_kernel(const float* __restrict__ x,
                const float* __restrict__ wq, const float* __restrict__ bq,
                const float* __restrict__ wk, const float* __restrict__ bk,
                const float* __restrict__ wv, const float* __restrict__ bv)
{
    __shared__ float w_s[3*432];
    __shared__ float b_s[3*36];
    const int t = threadIdx.x;
    const int b = blockIdx.y, nblk = blockIdx.x;
    const int n = nblk*128 + t;

    for (int i = t; i < 432; i += 128){ w_s[i]=wq[i]; w_s[432+i]=wk[i]; w_s[864+i]=wv[i]; }
    if (t < 36){ b_s[t]=bq[t]; b_s[36+t]=bk[t]; b_s[72+t]=bv[t]; }
    __syncthreads();

    float xv[12];
    #pragma unroll
    for (int c = 0; c < 12; ++c) xv[c] = x[(b*12 + c)*NN + n];

    float qv[36], kv[36];
    #pragma unroll 4
    for (int o = 0; o < 36; ++o){
        float q = b_s[o], k = b_s[36+o], v = b_s[72+o];
        #pragma unroll
        for (int c = 0; c < 12; ++c){
            q += w_s[o*12+c]*xv[c];
            k += w_s[432+o*12+c]*xv[c];
            v += w_s[864+o*12+c]*xv[c];
        }
        qv[o] = q*SCALE;
        kv[o] = k;
        g_v[((long)(b*48+o))*NN + n] = v;
    }
    #pragma unroll
    for (int o = 36; o < 48; ++o) g_v[((long)(b*48+o))*NN + n] = 0.f;

    const int base = (b*NB + nblk)*PANEL;
    /* A-frag coords for this thread's row r=t */
    const int rt = t >> 4, lr = t & 15, gA = lr & 7, half = lr >> 3;
    /* B-frag coords for this thread's col lc=t */
    const int ct = t >> 3, gB = t & 7;

    #pragma unroll
    for (int p = 0; p < 24; ++p){
        const int kk = p >> 3, cp = p & 7;
        const int regA = ((cp >> 2) << 1) | half;
        const int laneA = (gA << 2) | (cp & 3);
        const int aoff = ((rt*3 + kk)*2)*128 + laneA*4 + regA;
        const int regB = cp >> 2;
        const int laneB = (gB << 2) | (cp & 3);
        const int boff = ((ct*3 + kk)*2)*64 + laneB*2 + regB;
        const int c0 = 2*p, c1 = 2*p + 1;

        const float q0 = (c0 < 36) ? qv[c0] : 0.f, q1 = (c1 < 36) ? qv[c1] : 0.f;
        u32 hq, lq; splitpair(q0, q1, hq, lq);
        g_qA[base + aoff] = hq;  g_qA[base + aoff + 128] = lq;
        g_qB[base + boff] = hq;  g_qB[base + boff + 64]  = lq;

        const float k0 = (c0 < 36) ? kv[c0] : 0.f, k1 = (c1 < 36) ? kv[c1] : 0.f;
        u32 hk, lk; splitpair(k0, k1, hk, lk);
        g_kA[base + aoff] = hk;  g_kA[base + aoff + 128] = lk;
        g_kB[base + boff] = hk;  g_kB[base + boff + 64]  = lk;
    }
}

/* ========= Pass 1: D[n] = sum_m exp(s[n,m]); write vB = (v/D) frags ====== */
__global__ __launch_bounds__(128)
void pass1_kernel()
{
    __shared__ u32 sB[PANEL];
    __shared__ float Dsh[64];
    __shared__ float invd[64];

    const int t = threadIdx.x, w = t >> 5, lane = t & 31;
    const int g = lane >> 2, tg = lane & 3;
    const int b = blockIdx.y;
    const int nblk = blockIdx.x >> 1, half = blockIdx.x & 1;
    const int rt = half*4 + w;

    /* A fragments: K rows rt*16..+15 of this nblk */
    u32 ah[3][4], al[3][4];
    {
        const u32* kAb = g_kA + (b*NB + nblk)*PANEL;
        #pragma unroll
        for (int kk = 0; kk < 3; ++kk){
            uint4 h = *(const uint4*)(kAb + ((rt*3+kk)*2 + 0)*128 + lane*4);
            uint4 l = *(const uint4*)(kAb + ((rt*3+kk)*2 + 1)*128 + lane*4);
            ah[kk][0]=h.x; ah[kk][1]=h.y; ah[kk][2]=h.z; ah[kk][3]=h.w;
            al[kk][0]=l.x; al[kk][1]=l.y; al[kk][2]=l.z; al[kk][3]=l.w;
        }
    }

    float rs0 = 0.f, rs1 = 0.f;
    const u32* qBall = g_qB + b*NB*PANEL;

    for (int mc = 0; mc < NB; ++mc){
        __syncthreads();
        {
            const uint4* src = (const uint4*)(qBall + mc*PANEL);
            uint4* dst = (uint4*)sB;
            #pragma unroll
            for (int i = 0; i < 12; ++i) dst[t + i*128] = src[t + i*128];
        }
        __syncthreads();

        #pragma unroll 4
        for (int ctb = 0; ctb < 16; ++ctb){
            float acc[4] = {0.f, 0.f, 0.f, 0.f};
            u32 bh[3][2], bl[3][2];
            #pragma unroll
            for (int kk = 0; kk < 3; ++kk){
                uint2 h = *(const uint2*)(sB + ((ctb*3+kk)*2 + 0)*64 + lane*2);
                uint2 l = *(const uint2*)(sB + ((ctb*3+kk)*2 + 1)*64 + lane*2);
                bh[kk][0]=h.x; bh[kk][1]=h.y; bl[kk][0]=l.x; bl[kk][1]=l.y;
            }
            #pragma unroll
            for (int kk = 0; kk < 3; ++kk) mma_bf16(acc, ah[kk], bh[kk]);
            #pragma unroll
            for (int kk = 0; kk < 3; ++kk) mma_bf16(acc, ah[kk], bl[kk]);
            #pragma unroll
            for (int kk = 0; kk < 3; ++kk) mma_bf16(acc, al[kk], bh[kk]);

            rs0 += __expf(acc[0]) + __expf(acc[1]);
            rs1 += __expf(acc[2]) + __expf(acc[3]);
        }
    }

    rs0 += __shfl_xor_sync(0xFFFFFFFFu, rs0, 1);
    rs0 += __shfl_xor_sync(0xFFFFFFFFu, rs0, 2);
    rs1 += __shfl_xor_sync(0xFFFFFFFFu, rs1, 1);
    rs1 += __shfl_xor_sync(0xFFFFFFFFu, rs1, 2);
    if (tg == 0){ Dsh[w*16 + g] = rs0; Dsh[w*16 + 8 + g] = rs1; }
    __syncthreads();
    if (t < 64) invd[t] = 1.0f / Dsh[t];
    __syncthreads();

    /* write vB fragments for kk in [half*4, half*4+4) */
    {
        u32* vBb = g_vB + (b*NB + nblk)*PANEL;
        const float* vbase = g_v + (long)b*48*NN + nblk*128;
        for (int j = t; j < 1536; j += 128){
            const int r   = j & 1;
            const int ln  = (j >> 1) & 31;
            const int c6  = (j >> 6) % 6;
            const int kkL = (j >> 6) / 6;
            const int kk  = half*4 + kkL;
            const int g2 = ln >> 2, tg2 = ln & 3;
            const int c  = c6*8 + g2;
            const int n0 = kk*16 + r*8 + tg2*2;
            const float v0 = vbase[(long)c*NN + n0]     * invd[n0     - half*64];
            const float v1 = vbase[(long)c*NN + n0 + 1] * invd[n0 + 1 - half*64];
            u32 hi, lo; splitpair(v0, v1, hi, lo);
            const int bidx = ((kk*6 + c6)*2)*64 + ln*2 + r;
            vBb[bidx] = hi; vBb[bidx + 64] = lo;
        }
    }
}

/* ===== Pass 2: S^T -> exp (regs) -> PV mma -> output projection ========== */
__global__ __launch_bounds__(128)
void pass2_kernel(const float* __restrict__ wo, const float* __restrict__ bo,
                  float* __restrict__ out)
{
    extern __shared__ u32 dyn[];
    u32* sK = dyn;                      /* 6144 u32 */
    u32* sV = dyn + PANEL;              /* 6144 u32 */
    float* wo_s = (float*)(dyn + 2*PANEL);  /* 432 */
    float* bo_s = wo_s + 432;               /* 12  */

    const int t = threadIdx.x, w = t >> 5, lane = t & 31;
    const int g = lane >> 2, tg = lane & 3;
    const int b = blockIdx.y;
    const int mblk = blockIdx.x >> 1, half = blockIdx.x & 1;
    const int rt = half*4 + w;

    for (int i = t; i < 432; i += 128) wo_s[i] = wo[i];
    if (t < 12) bo_s[t] = bo[t];

    u32 ah[3][4], al[3][4];
    {
        const u32* qAb = g_qA + (b*NB + mblk)*PANEL;
        #pragma unroll
        for (int kk = 0; kk < 3; ++kk){
            uint4 h = *(const uint4*)(qAb + ((rt*3+kk)*2 + 0)*128 + lane*4);
            uint4 l = *(const uint4*)(qAb + ((rt*3+kk)*2 + 1)*128 + lane*4);
            ah[kk][0]=h.x; ah[kk][1]=h.y; ah[kk][2]=h.z; ah[kk][3]=h.w;
            al[kk][0]=l.x; al[kk][1]=l.y; al[kk][2]=l.z; al[kk][3]=l.w;
        }
    }

    float acc2[6][4];
    #pragma unroll
    for (int c = 0; c < 6; ++c)
        #pragma unroll
        for (int i = 0; i < 4; ++i) acc2[c][i] = 0.f;

    const u32* kBall = g_kB + b*NB*PANEL;
    const u32* vBall = g_vB + b*NB*PANEL;

    for (int nc = 0; nc < NB; ++nc){
        __syncthreads();
        {
            const uint4* srcK = (const uint4*)(kBall + nc*PANEL);
            const uint4* srcV = (const uint4*)(vBall + nc*PANEL);
            uint4* dK = (uint4*)sK; uint4* dV = (uint4*)sV;
            #pragma unroll
            for (int i = 0; i < 12; ++i){
                dK[t + i*128] = srcK[t + i*128];
                dV[t + i*128] = srcV[t + i*128];
            }
        }
        __syncthreads();

        /* S^T tiles -> exp -> P A-fragments (registers only) */
        u32 pa[8][4];
        #pragma unroll
        for (int j = 0; j < 8; ++j){
            float a0[4] = {0,0,0,0}, a1[4] = {0,0,0,0};
            #pragma unroll
            for (int sub = 0; sub < 2; ++sub){
                float* acc = sub ? a1 : a0;
                const int ctb = j*2 + sub;
                u32 bh[3][2], bl[3][2];
                #pragma unroll
                for (int kk = 0; kk < 3; ++kk){
                    uint2 h = *(const uint2*)(sK + ((ctb*3+kk)*2 + 0)*64 + lane*2);
                    uint2 l = *(const uint2*)(sK + ((ctb*3+kk)*2 + 1)*64 + lane*2);
                    bh[kk][0]=h.x; bh[kk][1]=h.y; bl[kk][0]=l.x; bl[kk][1]=l.y;
                }
                #pragma unroll
                for (int kk = 0; kk < 3; ++kk) mma_bf16(acc, ah[kk], bh[kk]);
                #pragma unroll
                for (int kk = 0; kk < 3; ++kk) mma_bf16(acc, ah[kk], bl[kk]);
                #pragma unroll
                for (int kk = 0; kk < 3; ++kk) mma_bf16(acc, al[kk], bh[kk]);
            }
            pa[j][0] = pk2(__expf(a0[0]), __expf(a0[1]));
            pa[j][1] = pk2(__expf(a0[2]), __expf(a0[3]));
            pa[j][2] = pk2(__expf(a1[0]), __expf(a1[1]));
            pa[j][3] = pk2(__expf(a1[2]), __expf(a1[3]));
        }

        /* PV: acc2[c] += P x vp_hi + P x vp_lo */
        #pragma unroll
        for (int kk = 0; kk < 8; ++kk){
            #pragma unroll
            for (int c = 0; c < 6; ++c){
                u32 vh[2], vl[2];
                uint2 h = *(const uint2*)(sV + ((kk*6+c)*2 + 0)*64 + lane*2);
                uint2 l = *(const uint2*)(sV + ((kk*6+c)*2 + 1)*64 + lane*2);
                vh[0]=h.x; vh[1]=h.y; vl[0]=l.x; vl[1]=l.y;
                mma_bf16(acc2[c], pa[kk], vh);
                mma_bf16(acc2[c], pa[kk], vl);
            }
        }
    }

    /* stage attn^T [64 rows x 48 c] and apply output projection */
    __syncthreads();
    float* attn = (float*)dyn;     /* 64*49 floats = 12.5KB, fits in sK/sV */
    #pragma unroll
    for (int c = 0; c < 6; ++c){
        const int lr0 = w*16 + g, lr1 = lr0 + 8, col = c*8 + 2*tg;
        attn[lr0*49 + col]     = acc2[c][0];
        attn[lr0*49 + col + 1] = acc2[c][1];
        attn[lr1*49 + col]     = acc2[c][2];
        attn[lr1*49 + col + 1] = acc2[c][3];
    }
    __syncthreads();
    {
        const int lr = t & 63, og = t >> 6;
        const int m = mblk*128 + half*64 + lr;
        #pragma unroll
        for (int oo = 0; oo < 6; ++oo){
            const int o = og*6 + oo;
            float acc = bo_s[o];
            #pragma unroll
            for (int c = 0; c < 36; ++c) acc += wo_s[o*36 + c]*attn[lr*49 + c];
            out[((long)(b*12 + o))*NN + m] = acc;
        }
    }
}

/* ============================== launch =================================== */
extern "C" void kernel_launch(void* const* d_in, const int* in_sizes, int n_in,
                              void* d_out, int out_size)
{
    const float* x  = (const float*)d_in[0];
    const float* wq = (const float*)d_in[1];
    const float* bq = (const float*)d_in[2];
    const float* wk = (const float*)d_in[3];
    const float* bk = (const float*)d_in[4];
    const float* wv = (const float*)d_in[5];
    const float* bv = (const float*)d_in[6];
    const float* wo = (const float*)d_in[7];
    const float* bo = (const float*)d_in[8];
    float* out = (float*)d_out;

    cudaFuncSetAttribute(pass2_kernel,
                         cudaFuncAttributeMaxDynamicSharedMemorySize, 50928);

    qkv_kernel  <<<dim3(NB, 8), 128>>>(x, wq, bq, wk, bk, wv, bv);
    pass1_kernel<<<dim3(64, 8), 128>>>();
    pass2_kernel<<<dim3(64, 8), 128, 50928>>>(wo, bo, out);
}

// round 4
// speedup vs baseline: 4.7628x; 1.8753x over previous
#include <cuda_runtime.h>
#include <cuda_fp16.h>
#include <cstdint>

#define NN 4096
#define NB 32
#define PA 3072      /* u32 per A/B fragment panel: 128 rows x 48 k, fp16 pairs */
#define PP 8192      /* u32 per P' panel: 128 n x 128 m fp16 */
#define SCALE2 (0.28867513459481287f * 1.4426950408889634f)  /* (1/sqrt12)*log2e */

typedef unsigned int u32;

/* ---------------- global scratch ----------------------------------------- */
__device__ __align__(16) u32   g_kA[8*NB*PA];        /* K as mma-A frags (pass1) */
__device__ __align__(16) u32   g_qB[8*NB*PA];        /* Q as mma-B frags (pass1) */
__device__ __align__(16) u32   g_vA[8*NB*PA];        /* v/D as mma-A frags (pass2) */
__device__ __align__(16) float g_v [8*48*NN];        /* fp32 v, rows 36..47 zero */
__device__ __align__(16) u32   g_P [67108864];       /* P' panels: 256MB */

/* ---------------- helpers ------------------------------------------------ */
__device__ __forceinline__ void mma_h(float* d, uint4 a, uint2 b){
    asm("mma.sync.aligned.m16n8k16.row.col.f32.f16.f16.f32 "
        "{%0,%1,%2,%3},{%4,%5,%6,%7},{%8,%9},{%0,%1,%2,%3};"
        : "+f"(d[0]), "+f"(d[1]), "+f"(d[2]), "+f"(d[3])
        : "r"(a.x), "r"(a.y), "r"(a.z), "r"(a.w), "r"(b.x), "r"(b.y));
}
__device__ __forceinline__ u32 pkh(float lo, float hi){
    __half2 h = __floats2half2_rn(lo, hi);     /* x = lo (low 16 bits) */
    return *(u32*)&h;
}
__device__ __forceinline__ float ex2f(float x){
    float r; asm("ex2.approx.f32 %0, %1;" : "=f"(r) : "f"(x)); return r;
}
__device__ __forceinline__ u32 smem_u32(const void* p){
    u32 a;
    asm("{ .reg .u64 t; cvta.to.shared.u64 t, %1; cvt.u32.u64 %0, t; }" : "=r"(a) : "l"(p));
    return a;
}
__device__ __forceinline__ void cpa16(u32 d, const void* s){
    asm volatile("cp.async.ca.shared.global [%0], [%1], 16;" :: "r"(d), "l"(s));
}
#define CP_COMMIT() asm volatile("cp.async.commit_group;")
#define CP_WAIT1()  asm volatile("cp.async.wait_group 1;")

/* ================= Kernel A: QKV -> fp16 fragment panels ================= */
__global__ __launch_bounds__(128)
void qkv_kernel(const float* __restrict__ x,
                const float* __restrict__ wq, const float* __restrict__ bq,
                const float* __restrict__ wk, const float* __restrict__ bk,
                const float* __restrict__ wv, const float* __restrict__ bv)
{
    __shared__ float w_s[3*432];
    __shared__ float b_s[3*36];
    const int t = threadIdx.x;
    const int b = blockIdx.y, nblk = blockIdx.x;
    const int n = nblk*128 + t;

    for (int i = t; i < 432; i += 128){ w_s[i]=wq[i]; w_s[432+i]=wk[i]; w_s[864+i]=wv[i]; }
    if (t < 36){ b_s[t]=bq[t]; b_s[36+t]=bk[t]; b_s[72+t]=bv[t]; }
    __syncthreads();

    float xv[12];
    #pragma unroll
    for (int c = 0; c < 12; ++c) xv[c] = x[(b*12 + c)*NN + n];

    float qv[36], kv[36];
    #pragma unroll 4
    for (int o = 0; o < 36; ++o){
        float q = b_s[o], k = b_s[36+o], v = b_s[72+o];
        #pragma unroll
        for (int c = 0; c < 12; ++c){
            q += w_s[o*12+c]*xv[c];
            k += w_s[432+o*12+c]*xv[c];
            v += w_s[864+o*12+c]*xv[c];
        }
        qv[o] = q*SCALE2;   /* fold softmax scale AND log2e: ex2 later */
        kv[o] = k;
        g_v[((long)(b*48+o))*NN + n] = v;
    }
    #pragma unroll
    for (int o = 36; o < 48; ++o) g_v[((long)(b*48+o))*NN + n] = 0.f;

    const int base = (b*NB + nblk)*PA;
    const int rt = t >> 4, lr = t & 15;     /* A coords: row r = t */
    const int ct = t >> 3, gB = t & 7;      /* B coords: col = t  */

    #pragma unroll
    for (int p = 0; p < 24; ++p){
        const int kk = p >> 3, cp = p & 7;
        const int c0 = kk*16 + cp*2, c1 = c0 + 1;
        const float k0 = (c0 < 36) ? kv[c0] : 0.f, k1 = (c1 < 36) ? kv[c1] : 0.f;
        const float q0 = (c0 < 36) ? qv[c0] : 0.f, q1 = (c1 < 36) ? qv[c1] : 0.f;
        /* A-frag (K) */
        const int regA  = ((cp >> 2) << 1) | (lr >> 3);
        const int laneA = ((lr & 7) << 2) | (cp & 3);
        g_kA[base + (rt*3 + kk)*128 + laneA*4 + regA] = pkh(k0, k1);
        /* B-frag (Q) */
        const int regB  = cp >> 2;
        const int laneB = (gB << 2) | (cp & 3);
        g_qB[base + (ct*3 + kk)*64 + laneB*2 + regB] = pkh(q0, q1);
    }
}

/* ====== Pass 1: S=K^TQ -> P'=2^s (fp16, B-frag panels), D, vp frags ====== */
__global__ __launch_bounds__(256)
void pass1_kernel()
{
    extern __shared__ char smraw[];
    u32*  qb0  = (u32*)smraw;          /* 3072 u32 */
    u32*  qb1  = qb0 + PA;             /* 3072 u32 */
    u32*  p_s  = qb1 + PA;             /* 128*65 = 8320 u32 */
    float* Dsh  = (float*)(p_s + 8320);/* 128 */
    float* invd = Dsh + 128;           /* 128 */

    const int t = threadIdx.x, w = t >> 5, lane = t & 31;
    const int g = lane >> 2, tg = lane & 3;
    const int b = blockIdx.y, nblk = blockIdx.x;

    /* K A-frags: warp w owns n-rows w*16..+15 */
    uint4 a[3];
    {
        const u32* kA = g_kA + (b*NB + nblk)*PA;
        #pragma unroll
        for (int kk = 0; kk < 3; ++kk)
            a[kk] = *(const uint4*)(kA + (w*3 + kk)*128 + lane*4);
    }

    const char* qsrc = (const char*)(g_qB + (long)b*NB*PA);
    {   /* prologue: chunk 0 */
        const u32 d = smem_u32(qb0);
        for (int i = t; i < 768; i += 256) cpa16(d + i*16, qsrc + i*16);
    }
    CP_COMMIT();

    float rs0 = 0.f, rs1 = 0.f;

    for (int mc = 0; mc < NB; ++mc){
        u32* cur = (mc & 1) ? qb1 : qb0;
        if (mc + 1 < NB){
            const u32 d = smem_u32((mc & 1) ? qb0 : qb1);
            const char* s = qsrc + (long)(mc + 1)*PA*4;
            for (int i = t; i < 768; i += 256) cpa16(d + i*16, s + i*16);
        }
        CP_COMMIT();
        CP_WAIT1();
        __syncthreads();

        #pragma unroll 4
        for (int ctb = 0; ctb < 16; ++ctb){
            float acc[4] = {0.f, 0.f, 0.f, 0.f};
            #pragma unroll
            for (int kk = 0; kk < 3; ++kk){
                uint2 bq = *(const uint2*)(cur + (ctb*3 + kk)*64 + lane*2);
                mma_h(acc, a[kk], bq);
            }
            const float e0 = ex2f(fminf(acc[0], 15.f));
            const float e1 = ex2f(fminf(acc[1], 15.f));
            const float e2 = ex2f(fminf(acc[2], 15.f));
            const float e3 = ex2f(fminf(acc[3], 15.f));
            rs0 += e0 + e1;
            rs1 += e2 + e3;
            p_s[(w*16 + g)*65 + ctb*4 + tg]     = pkh(e0, e1);
            p_s[(w*16 + 8 + g)*65 + ctb*4 + tg] = pkh(e2, e3);
        }
        __syncthreads();

        /* reorder p_s -> P' B-frag panel, coalesced STG */
        u32* dst = g_P + ((long)((b*NB + mc)*NB + nblk))*PP;
        for (int j = t; j < PP; j += 256){
            const int kk = j >> 10, ctj = (j >> 6) & 15;
            const int l2 = (j >> 1) & 31, reg = j & 1;
            const int g2 = l2 >> 2, tg2 = l2 & 3;
            const int n0 = kk*16 + reg*8 + tg2*2;
            const int col = ctj*4 + (g2 >> 1);
            const u32 xa = p_s[n0*65 + col];
            const u32 xb = p_s[(n0 + 1)*65 + col];
            u32 r;
            if (g2 & 1) asm("prmt.b32 %0,%1,%2,0x7632;" : "=r"(r) : "r"(xa), "r"(xb));
            else        asm("prmt.b32 %0,%1,%2,0x5410;" : "=r"(r) : "r"(xa), "r"(xb));
            dst[j] = r;
        }
    }

    /* reduce D over tg lanes (m-cols) */
    rs0 += __shfl_xor_sync(0xFFFFFFFFu, rs0, 1);
    rs0 += __shfl_xor_sync(0xFFFFFFFFu, rs0, 2);
    rs1 += __shfl_xor_sync(0xFFFFFFFFu, rs1, 1);
    rs1 += __shfl_xor_sync(0xFFFFFFFFu, rs1, 2);
    if (tg == 0){ Dsh[w*16 + g] = rs0; Dsh[w*16 + 8 + g] = rs1; }
    __syncthreads();
    if (t < 128) invd[t] = 1.0f / Dsh[t];
    __syncthreads();

    /* vp = v/D as A-frag panel (fp16 single term) */
    {
        u32* vdst = g_vA + (b*NB + nblk)*PA;
        const float* vb = g_v + (long)b*48*NN + nblk*128;
        for (int j = t; j < PA; j += 256){
            const int q7 = j >> 7;
            const int kk = q7/3, rt2 = q7 - kk*3;
            const int ln = (j >> 2) & 31, rg = j & 3;
            const int c  = rt2*16 + (rg & 1)*8 + (ln >> 2);
            const int nl = kk*16 + (rg >> 1)*8 + (ln & 3)*2;
            const float2 vv = *(const float2*)(vb + (long)c*NN + nl);
            vdst[j] = pkh(vv.x*invd[nl], vv.y*invd[nl + 1]);
        }
    }
}

/* ====== Pass 2: attnT[c,m] = sum_n vp[c,n] P'[n,m]; output projection ==== */
__global__ __launch_bounds__(256)
void pass2_kernel(const float* __restrict__ wo, const float* __restrict__ bo,
                  float* __restrict__ out)
{
    extern __shared__ char smraw[];
    u32* pb0 = (u32*)smraw;            /* 8192 u32 */
    u32* pb1 = pb0 + PP;               /* 8192 u32 */
    u32* vb0 = pb1 + PP;               /* 3072 u32 */
    u32* vb1 = vb0 + PA;               /* 3072 u32 */
    float* wo_s = (float*)(vb1 + PA);  /* 432 */
    float* bo_s = wo_s + 432;          /* 12  */

    const int t = threadIdx.x, w = t >> 5, lane = t & 31;
    const int g = lane >> 2, tg = lane & 3;
    const int b = blockIdx.y, mt = blockIdx.x;

    for (int i = t; i < 432; i += 256) wo_s[i] = wo[i];
    if (t < 12) bo_s[t] = bo[t];

    const char* psrc = (const char*)(g_P + ((long)(b*NB + mt)*NB)*PP);
    const char* vsrc = (const char*)(g_vA + (long)b*NB*PA);

    {   /* prologue: chunk 0 */
        const u32 dp = smem_u32(pb0), dv = smem_u32(vb0);
        for (int i = t; i < 2048; i += 256) cpa16(dp + i*16, psrc + i*16);
        for (int i = t; i < 768;  i += 256) cpa16(dv + i*16, vsrc + i*16);
    }
    CP_COMMIT();

    float acc[3][2][4];
    #pragma unroll
    for (int rt = 0; rt < 3; ++rt)
        #pragma unroll
        for (int cc = 0; cc < 2; ++cc)
            #pragma unroll
            for (int i = 0; i < 4; ++i) acc[rt][cc][i] = 0.f;

    const int ct0 = w*2, ct1 = w*2 + 1;

    for (int nc = 0; nc < NB; ++nc){
        u32* curp = (nc & 1) ? pb1 : pb0;
        u32* curv = (nc & 1) ? vb1 : vb0;
        if (nc + 1 < NB){
            const u32 dp = smem_u32((nc & 1) ? pb0 : pb1);
            const u32 dv = smem_u32((nc & 1) ? vb0 : vb1);
            const char* sp = psrc + (long)(nc + 1)*PP*4;
            const char* sv = vsrc + (long)(nc + 1)*PA*4;
            for (int i = t; i < 2048; i += 256) cpa16(dp + i*16, sp + i*16);
            for (int i = t; i < 768;  i += 256) cpa16(dv + i*16, sv + i*16);
        }
        CP_COMMIT();
        CP_WAIT1();
        __syncthreads();

        #pragma unroll
        for (int kk = 0; kk < 8; ++kk){
            uint4 av[3];
            #pragma unroll
            for (int rt = 0; rt < 3; ++rt)
                av[rt] = *(const uint4*)(curv + (kk*3 + rt)*128 + lane*4);
            const uint2 b0 = *(const uint2*)(curp + (kk*16 + ct0)*64 + lane*2);
            const uint2 b1 = *(const uint2*)(curp + (kk*16 + ct1)*64 + lane*2);
            #pragma unroll
            for (int rt = 0; rt < 3; ++rt){
                mma_h(acc[rt][0], av[rt], b0);
                mma_h(acc[rt][1], av[rt], b1);
            }
        }
        __syncthreads();   /* all warps done with curp/curv before overwrite */
    }

    /* stage attn^T [48c x 128m] fp32, then output projection */
    float* attn = (float*)smraw;       /* 48*132*4 = 25.3KB, fits in pb0/pb1 */
    #pragma unroll
    for (int rt = 0; rt < 3; ++rt)
        #pragma unroll
        for (int cc = 0; cc < 2; ++cc){
            const int r0 = rt*16 + g, r1 = r0 + 8;
            const int mcol = (w*2 + cc)*8 + tg*2;
            attn[r0*132 + mcol]     = acc[rt][cc][0];
            attn[r0*132 + mcol + 1] = acc[rt][cc][1];
            attn[r1*132 + mcol]     = acc[rt][cc][2];
            attn[r1*132 + mcol + 1] = acc[rt][cc][3];
        }
    __syncthreads();
    {
        const int og = t >> 7, m = t & 127;
        #pragma unroll
        for (int oo = 0; oo < 6; ++oo){
            const int o = og*6 + oo;
            float s = bo_s[o];
            #pragma unroll
            for (int c = 0; c < 36; ++c) s += wo_s[o*36 + c]*attn[c*132 + m];
            out[((long)(b*12 + o))*NN + mt*128 + m] = s;
        }
    }
}

/* ============================== launch =================================== */
extern "C" void kernel_launch(void* const* d_in, const int* in_sizes, int n_in,
                              void* d_out, int out_size)
{
    const float* x  = (const float*)d_in[0];
    const float* wq = (const float*)d_in[1];
    const float* bq = (const float*)d_in[2];
    const float* wk = (const float*)d_in[3];
    const float* bk = (const float*)d_in[4];
    const float* wv = (const float*)d_in[5];
    const float* bv = (const float*)d_in[6];
    const float* wo = (const float*)d_in[7];
    const float* bo = (const float*)d_in[8];
    float* out = (float*)d_out;

    cudaFuncSetAttribute(pass1_kernel,
                         cudaFuncAttributeMaxDynamicSharedMemorySize, 58880);
    cudaFuncSetAttribute(pass2_kernel,
                         cudaFuncAttributeMaxDynamicSharedMemorySize, 91968);

    qkv_kernel  <<<dim3(NB, 8), 128>>>(x, wq, bq, wk, bk, wv, bv);
    pass1_kernel<<<dim3(NB, 8), 256, 58880>>>();
    pass2_kernel<<<dim3(NB, 8), 256, 91968>>>(wo, bo, out);
}

// round 5
// speedup vs baseline: 6.2425x; 1.3107x over previous
#include <cuda_runtime.h>
#include <cuda_fp16.h>
#include <cstdint>

#define NN 4096
#define NB 32
#define PA 3072      /* u32 per B-frag panel: 128 cols x 48 k fp16 pairs */
#define SCALE2 (0.28867513459481287f * 1.4426950408889634f)  /* (1/sqrt12)*log2e */

typedef unsigned int u32;

/* ---------------- global scratch ----------------------------------------- */
__device__ __align__(16) u32   g_qA[8*NB*PA];     /* Q as mma-A frags (pass1) */
__device__ __align__(16) u32   g_kB[8*NB*PA];     /* K as mma-B frags (pass1) */
__device__ __align__(16) u32   g_vB[8*NB*PA];     /* v/D as mma-B frags (pass2) */
__device__ __align__(16) float g_v [8*48*NN];     /* fp32 v, rows 36..47 zero */
__device__ __align__(16) float g_Dp[8*NB*NN];     /* per-mtile partial D sums */
__device__ __align__(16) uint4 g_P [16777216];    /* P' A-frags: 256MB */

/* ---------------- helpers ------------------------------------------------ */
__device__ __forceinline__ void mma_h(float* d, uint4 a, uint2 b){
    asm("mma.sync.aligned.m16n8k16.row.col.f32.f16.f16.f32 "
        "{%0,%1,%2,%3},{%4,%5,%6,%7},{%8,%9},{%0,%1,%2,%3};"
        : "+f"(d[0]), "+f"(d[1]), "+f"(d[2]), "+f"(d[3])
        : "r"(a.x), "r"(a.y), "r"(a.z), "r"(a.w), "r"(b.x), "r"(b.y));
}
__device__ __forceinline__ u32 pkh(float lo, float hi){
    __half2 h = __floats2half2_rn(lo, hi);
    return *(u32*)&h;
}
__device__ __forceinline__ float ex2f(float x){
    float r; asm("ex2.approx.f32 %0, %1;" : "=f"(r) : "f"(x)); return r;
}
__device__ __forceinline__ u32 smem_u32(const void* p){
    u32 a;
    asm("{ .reg .u64 t; cvta.to.shared.u64 t, %1; cvt.u32.u64 %0, t; }" : "=r"(a) : "l"(p));
    return a;
}
__device__ __forceinline__ void cpa16(u32 d, const void* s){
    asm volatile("cp.async.ca.shared.global [%0], [%1], 16;" :: "r"(d), "l"(s));
}
#define CP_COMMIT() asm volatile("cp.async.commit_group;")
#define CP_WAIT1()  asm volatile("cp.async.wait_group 1;")

/* ================= Kernel A: QKV -> fp16 fragment panels ================= */
__global__ __launch_bounds__(128)
void qkv_kernel(const float* __restrict__ x,
                const float* __restrict__ wq, const float* __restrict__ bq,
                const float* __restrict__ wk, const float* __restrict__ bk,
                const float* __restrict__ wv, const float* __restrict__ bv)
{
    __shared__ float w_s[3*432];
    __shared__ float b_s[3*36];
    const int t = threadIdx.x;
    const int b = blockIdx.y, nblk = blockIdx.x;
    const int n = nblk*128 + t;

    for (int i = t; i < 432; i += 128){ w_s[i]=wq[i]; w_s[432+i]=wk[i]; w_s[864+i]=wv[i]; }
    if (t < 36){ b_s[t]=bq[t]; b_s[36+t]=bk[t]; b_s[72+t]=bv[t]; }
    __syncthreads();

    float xv[12];
    #pragma unroll
    for (int c = 0; c < 12; ++c) xv[c] = x[(b*12 + c)*NN + n];

    float qv[36], kv[36];
    #pragma unroll 4
    for (int o = 0; o < 36; ++o){
        float q = b_s[o], k = b_s[36+o], v = b_s[72+o];
        #pragma unroll
        for (int c = 0; c < 12; ++c){
            q += w_s[o*12+c]*xv[c];
            k += w_s[432+o*12+c]*xv[c];
            v += w_s[864+o*12+c]*xv[c];
        }
        qv[o] = q*SCALE2;   /* fold softmax scale AND log2e */
        kv[o] = k;
        g_v[((long)(b*48+o))*NN + n] = v;
    }
    #pragma unroll
    for (int o = 36; o < 48; ++o) g_v[((long)(b*48+o))*NN + n] = 0.f;

    const int base = (b*NB + nblk)*PA;
    const int rt = t >> 4, lr = t & 15;     /* A coords: row (m) = t */
    const int ct = t >> 3, gB = t & 7;      /* B coords: col (n) = t */

    #pragma unroll
    for (int p = 0; p < 24; ++p){
        const int kk = p >> 3, cp = p & 7;
        const int c0 = kk*16 + cp*2, c1 = c0 + 1;
        const float q0 = (c0 < 36) ? qv[c0] : 0.f, q1 = (c1 < 36) ? qv[c1] : 0.f;
        const float k0 = (c0 < 36) ? kv[c0] : 0.f, k1 = (c1 < 36) ? kv[c1] : 0.f;
        /* Q -> A-frag */
        const int regA  = ((cp >> 2) << 1) | (lr >> 3);
        const int laneA = ((lr & 7) << 2) | (cp & 3);
        g_qA[base + (rt*3 + kk)*128 + laneA*4 + regA] = pkh(q0, q1);
        /* K -> B-frag */
        const int regB  = cp >> 2;
        const int laneB = (gB << 2) | (cp & 3);
        g_kB[base + (ct*3 + kk)*64 + laneB*2 + regB] = pkh(k0, k1);
    }
}

/* ====== Pass 1: S = Q·K^T (m rows) -> P' A-frags + partial D[n] ========== */
__global__ __launch_bounds__(256)
void pass1_kernel()
{
    extern __shared__ char smraw[];
    u32* kb0 = (u32*)smraw;                 /* 3072 u32 */
    u32* kb1 = kb0 + PA;                    /* 3072 u32 */
    float2* Dp2 = (float2*)(kb1 + PA);      /* [64 colpair][66] float2 = 33792B */

    const int t = threadIdx.x, w = t >> 5, lane = t & 31;
    const int g = lane >> 2, tg = lane & 3;
    const int b = blockIdx.y, mt = blockIdx.x;

    /* Q A-frags: warp w owns m-rows w*16..+15 */
    uint4 aq[3];
    {
        const u32* qA = g_qA + (b*NB + mt)*PA;
        #pragma unroll
        for (int ck = 0; ck < 3; ++ck)
            aq[ck] = *(const uint4*)(qA + (w*3 + ck)*128 + lane*4);
    }

    const char* ksrc = (const char*)(g_kB + (long)b*NB*PA);
    { const u32 d = smem_u32(kb0); for (int i = t; i < 768; i += 256) cpa16(d + i*16, ksrc + i*16); }
    CP_COMMIT();

    for (int nc = 0; nc < NB; ++nc){
        u32* cur = (nc & 1) ? kb1 : kb0;
        if (nc + 1 < NB){
            const u32 d = smem_u32((nc & 1) ? kb0 : kb1);
            const char* s = ksrc + (long)(nc + 1)*PA*4;
            for (int i = t; i < 768; i += 256) cpa16(d + i*16, s + i*16);
        }
        CP_COMMIT(); CP_WAIT1();
        __syncthreads();

        uint4* dst = g_P + (((long)(b*NB + mt)*NB + nc)*8 + w)*256 + lane;

        #pragma unroll
        for (int kk = 0; kk < 8; ++kk){
            float a0[4] = {0.f,0.f,0.f,0.f}, a1[4] = {0.f,0.f,0.f,0.f};
            #pragma unroll
            for (int ck = 0; ck < 3; ++ck){
                const uint2 b0 = *(const uint2*)(cur + ((2*kk    )*3 + ck)*64 + lane*2);
                const uint2 b1 = *(const uint2*)(cur + ((2*kk + 1)*3 + ck)*64 + lane*2);
                mma_h(a0, aq[ck], b0);
                mma_h(a1, aq[ck], b1);
            }
            const float e00 = ex2f(fminf(a0[0],15.f)), e01 = ex2f(fminf(a0[1],15.f));
            const float e02 = ex2f(fminf(a0[2],15.f)), e03 = ex2f(fminf(a0[3],15.f));
            const float e10 = ex2f(fminf(a1[0],15.f)), e11 = ex2f(fminf(a1[1],15.f));
            const float e12 = ex2f(fminf(a1[2],15.f)), e13 = ex2f(fminf(a1[3],15.f));
            /* output-fragment == A-frag identity: direct STG.128, streaming */
            uint4 pv;
            pv.x = pkh(e00, e01); pv.y = pkh(e02, e03);
            pv.z = pkh(e10, e11); pv.w = pkh(e12, e13);
            __stcs(dst + kk*32, pv);
            /* column (n) partial sums over this thread's two rows */
            Dp2[(8*kk     + tg)*66 + w*8 + g] = make_float2(e00 + e02, e01 + e03);
            Dp2[(8*kk + 4 + tg)*66 + w*8 + g] = make_float2(e10 + e12, e11 + e13);
        }
        __syncthreads();
        if (t < 64){
            const float4* p = (const float4*)(Dp2 + t*66);
            float sx = 0.f, sy = 0.f;
            #pragma unroll
            for (int i = 0; i < 32; ++i){ const float4 f = p[i]; sx += f.x + f.z; sy += f.y + f.w; }
            *(float2*)(g_Dp + (b*NB + mt)*NN + nc*128 + t*2) = make_float2(sx, sy);
        }
        __syncthreads();
    }
}

/* ====== vp kernel: D reduce over mtiles, write vp = v/D as B-frags ======= */
__global__ __launch_bounds__(128)
void vp_kernel()
{
    __shared__ float invd[128];
    const int t = threadIdx.x, b = blockIdx.y, ncb = blockIdx.x;
    float s = 0.f;
    for (int mtt = 0; mtt < NB; ++mtt)
        s += g_Dp[(b*NB + mtt)*NN + ncb*128 + t];
    invd[t] = 1.f/s;
    __syncthreads();

    u32* vdst = g_vB + (b*NB + ncb)*PA;
    const float* vb = g_v + (long)b*48*NN + ncb*128;
    for (int j = t; j < PA; j += 128){
        const int reg = j & 1, l5 = (j >> 1) & 31, tile = j >> 6;
        const int kk = tile/6, ct = tile - 6*kk;
        const int c  = ct*8 + (l5 >> 2);
        const int nl = kk*16 + (l5 & 3)*2 + reg*8;
        const float2 vv = *(const float2*)(vb + (long)c*NN + nl);
        vdst[j] = pkh(vv.x*invd[nl], vv.y*invd[nl + 1]);
    }
}

/* ====== Pass 2: attnT[m,c] = sum_n P'[m,n]·vp[n,c]; output projection ==== */
__global__ __launch_bounds__(256)
void pass2_kernel(const float* __restrict__ wo, const float* __restrict__ bo,
                  float* __restrict__ out)
{
    extern __shared__ char smraw[];
    u32* vb0 = (u32*)smraw;                 /* 3072 u32 */
    u32* vb1 = vb0 + PA;                    /* 3072 u32 */
    float* wo_s = (float*)(vb1 + PA);       /* 432 */
    float* bo_s = wo_s + 432;               /* 12 + pad */
    float* attn = bo_s + 16;                /* 48*132 floats */

    const int t = threadIdx.x, w = t >> 5, lane = t & 31;
    const int g = lane >> 2, tg = lane & 3;
    const int b = blockIdx.y, mt = blockIdx.x;

    for (int i = t; i < 432; i += 256) wo_s[i] = wo[i];
    if (t < 12) bo_s[t] = bo[t];

    const char* vsrc = (const char*)(g_vB + (long)b*NB*PA);
    const uint4* pb  = g_P + ((long)(b*NB + mt)*NB*8)*256;

    uint4 pr[2][8];
    {
        const uint4* p0 = pb + w*256 + lane;
        #pragma unroll
        for (int kk = 0; kk < 8; ++kk) pr[0][kk] = __ldcs(p0 + kk*32);
        const u32 d = smem_u32(vb0);
        for (int i = t; i < 768; i += 256) cpa16(d + i*16, vsrc + i*16);
    }
    CP_COMMIT();

    float acc[6][4];
    #pragma unroll
    for (int ct = 0; ct < 6; ++ct)
        #pragma unroll
        for (int i = 0; i < 4; ++i) acc[ct][i] = 0.f;

    #pragma unroll 2
    for (int nc = 0; nc < NB; ++nc){
        const int cur = nc & 1;
        u32* vcur = cur ? vb1 : vb0;
        if (nc + 1 < NB){
            const uint4* pn = pb + ((nc + 1)*8 + w)*256 + lane;
            #pragma unroll
            for (int kk = 0; kk < 8; ++kk) pr[cur ^ 1][kk] = __ldcs(pn + kk*32);
            const u32 d = smem_u32(cur ? vb0 : vb1);
            const char* s = vsrc + (long)(nc + 1)*PA*4;
            for (int i = t; i < 768; i += 256) cpa16(d + i*16, s + i*16);
        }
        CP_COMMIT(); CP_WAIT1();
        __syncthreads();

        #pragma unroll
        for (int kk = 0; kk < 8; ++kk){
            #pragma unroll
            for (int ct = 0; ct < 6; ++ct){
                const uint2 bv = *(const uint2*)(vcur + (kk*6 + ct)*64 + lane*2);
                mma_h(acc[ct], pr[cur][kk], bv);
            }
        }
        __syncthreads();
    }

    /* stage attn^T [48c x 132m], then output projection */
    #pragma unroll
    for (int ct = 0; ct < 6; ++ct){
        const int m0 = w*16 + g, cb = ct*8 + 2*tg;
        attn[cb*132 + m0]         = acc[ct][0];
        attn[(cb + 1)*132 + m0]   = acc[ct][1];
        attn[cb*132 + m0 + 8]     = acc[ct][2];
        attn[(cb + 1)*132 + m0 + 8] = acc[ct][3];
    }
    __syncthreads();
    {
        const int og = t >> 7, m = t & 127;
        #pragma unroll
        for (int oo = 0; oo < 6; ++oo){
            const int o = og*6 + oo;
            float s = bo_s[o];
            #pragma unroll
            for (int c = 0; c < 36; ++c) s += wo_s[o*36 + c]*attn[c*132 + m];
            out[((long)(b*12 + o))*NN + mt*128 + m] = s;
        }
    }
}

/* ============================== launch =================================== */
extern "C" void kernel_launch(void* const* d_in, const int* in_sizes, int n_in,
                              void* d_out, int out_size)
{
    const float* x  = (const float*)d_in[0];
    const float* wq = (const float*)d_in[1];
    const float* bq = (const float*)d_in[2];
    const float* wk = (const float*)d_in[3];
    const float* bk = (const float*)d_in[4];
    const float* wv = (const float*)d_in[5];
    const float* bv = (const float*)d_in[6];
    const float* wo = (const float*)d_in[7];
    const float* bo = (const float*)d_in[8];
    float* out = (float*)d_out;

    /* pass1: 24576 + 33792 = 58368; pass2: 24576 + 1792 + 25344 = 51712 */
    cudaFuncSetAttribute(pass1_kernel,
                         cudaFuncAttributeMaxDynamicSharedMemorySize, 58368);
    cudaFuncSetAttribute(pass2_kernel,
                         cudaFuncAttributeMaxDynamicSharedMemorySize, 51712);

    qkv_kernel  <<<dim3(NB, 8), 128>>>(x, wq, bq, wk, bk, wv, bv);
    pass1_kernel<<<dim3(NB, 8), 256, 58368>>>();
    vp_kernel   <<<dim3(NB, 8), 128>>>();
    pass2_kernel<<<dim3(NB, 8), 256, 51712>>>(wo, bo, out);
}